// round 4
// baseline (speedup 1.0000x reference)
#include <cuda_runtime.h>

// Depthwise 3x3 conv, SAME padding, channel multiplier 2, NHWC fp32.
// x: [16,224,224,96], kernel: [3,3,1,2], bias: [192], out: [16,224,224,192]
// out[b,h,w,c*2+m] = sum_{dh,dw} x[b,h+dh-1,w+dw-1,c] * k[dh,dw,0,m] + bias[c*2+m]
//
// R4: R2 structure (WPT=4 best so far) + weights/bias in __constant__ memory.
// Uniform operands go to the uniform register file (LDCU/UR on sm_103a),
// freeing ~18 vector regs -> more CTAs/SM. R3 showed occupancy > traffic here.

#define BATCH 16
#define HH 224
#define WW 224
#define CIN 96
#define MULT 2
#define COUT (CIN * MULT)
#define WPT 4   // w-outputs per thread

__constant__ float c_ker[18];                    // [3][3][2]
__constant__ __align__(16) float c_bias[192];

// block: (24, 8) -> 24 float4-channel lanes x 8 w-groups (each 4 wide) = 32 w/block
// grid:  (224/32=7, 224, 16)
__global__ __launch_bounds__(192, 7) void dwconv_kernel(
    const float* __restrict__ x,
    float* __restrict__ out)
{
    const int c4 = threadIdx.x;                            // 0..23
    const int w0 = (blockIdx.x * 8 + threadIdx.y) * WPT;   // 0..220 step 4
    const int h  = blockIdx.y;
    const int b  = blockIdx.z;

    // acc[j][c][m]: 4 outputs x 4 channels x 2 mult = 32 floats
    float acc[WPT][4][2];
#pragma unroll
    for (int j = 0; j < WPT; j++)
#pragma unroll
        for (int c = 0; c < 4; c++) {
            acc[j][c][0] = 0.f;
            acc[j][c][1] = 0.f;
        }

    const float4 zero4 = make_float4(0.f, 0.f, 0.f, 0.f);

#pragma unroll
    for (int dh = 0; dh < 3; dh++) {
        const int hh = h + dh - 1;
        if ((unsigned)hh < (unsigned)HH) {
            const float* rp =
                x + (((size_t)b * HH + hh) * WW + w0) * CIN + 4 * c4;

            // Load 6 consecutive w positions: w0-1 .. w0+4 (batched -> MLP=6)
            float4 v[WPT + 2];
            v[0] = (w0 >= 1) ? *reinterpret_cast<const float4*>(rp - CIN) : zero4;
#pragma unroll
            for (int t = 1; t <= WPT; t++)
                v[t] = *reinterpret_cast<const float4*>(rp + (t - 1) * CIN);
            v[WPT + 1] = (w0 + WPT < WW)
                             ? *reinterpret_cast<const float4*>(rp + WPT * CIN)
                             : zero4;

#pragma unroll
            for (int j = 0; j < WPT; j++) {
#pragma unroll
                for (int dw = 0; dw < 3; dw++) {
                    const float4 xv = v[j + dw];
#pragma unroll
                    for (int m = 0; m < 2; m++) {
                        const float k = c_ker[(dh * 3 + dw) * 2 + m];  // uniform -> UR
                        acc[j][0][m] = fmaf(xv.x, k, acc[j][0][m]);
                        acc[j][1][m] = fmaf(xv.y, k, acc[j][1][m]);
                        acc[j][2][m] = fmaf(xv.z, k, acc[j][2][m]);
                        acc[j][3][m] = fmaf(xv.w, k, acc[j][3][m]);
                    }
                }
            }
        }
    }

    // bias: thread c4 covers output channels [8*c4, 8*c4+8)
    const float4 b0 = *reinterpret_cast<const float4*>(&c_bias[8 * c4]);
    const float4 b1 = *reinterpret_cast<const float4*>(&c_bias[8 * c4 + 4]);

    const size_t obase0 = (((size_t)b * HH + h) * WW + w0) * COUT + 8 * c4;
#pragma unroll
    for (int j = 0; j < WPT; j++) {
        // interleaved output ordering: oc = c*2 + m
        const float4 s0 = make_float4(acc[j][0][0] + b0.x, acc[j][0][1] + b0.y,
                                      acc[j][1][0] + b0.z, acc[j][1][1] + b0.w);
        const float4 s1 = make_float4(acc[j][2][0] + b1.x, acc[j][2][1] + b1.y,
                                      acc[j][3][0] + b1.z, acc[j][3][1] + b1.w);
        const size_t obase = obase0 + (size_t)j * COUT;
        *reinterpret_cast<float4*>(&out[obase])     = s0;
        *reinterpret_cast<float4*>(&out[obase + 4]) = s1;
    }
}

extern "C" void kernel_launch(void* const* d_in, const int* in_sizes, int n_in,
                              void* d_out, int out_size) {
    const float* x = (const float*)d_in[0];
    float* out     = (float*)d_out;

    // Uniform parameters -> constant memory (graph-capturable async D2D copies).
    cudaMemcpyToSymbolAsync(c_ker, d_in[1], 18 * sizeof(float), 0,
                            cudaMemcpyDeviceToDevice, 0);
    cudaMemcpyToSymbolAsync(c_bias, d_in[2], 192 * sizeof(float), 0,
                            cudaMemcpyDeviceToDevice, 0);

    dim3 block(24, 8, 1);
    dim3 grid(WW / (8 * WPT), HH, BATCH);
    dwconv_kernel<<<grid, block>>>(x, out);
}

// round 5
// speedup vs baseline: 1.6500x; 1.6500x over previous
#include <cuda_runtime.h>

// Depthwise 3x3 conv, SAME padding, channel multiplier 2, NHWC fp32.
// x: [16,224,224,96], kernel: [3,3,1,2], bias: [192], out: [16,224,224,192]
// out[b,h,w,c*2+m] = sum_{dh,dw} x[b,h+dh-1,w+dw-1,c] * k[dh,dw,0,m] + bias[c*2+m]
//
// R5: R2 structure (WPT=4, weights in REGISTERS — R4 showed LDC inner-loop is
// an 8-cyc/SMSP serialized port on sm_103a, never again). Occupancy lever:
// 96-thread CTAs + launch_bounds(96,12) -> reg cap 56, 12 CTAs/SM = 36 warps
// (vs R2's 5x192 = 30 warps). Same per-thread memory behavior as R2.

#define BATCH 16
#define HH 224
#define WW 224
#define CIN 96
#define MULT 2
#define COUT (CIN * MULT)
#define WPT 4   // w-outputs per thread

// block: (24, 4) -> 24 float4-channel lanes x 4 w-groups (each 4 wide) = 16 w/block
// grid:  (224/16=14, 224, 16)
__global__ __launch_bounds__(96, 12) void dwconv_kernel(
    const float* __restrict__ x,
    const float* __restrict__ ker,   // 18 floats
    const float* __restrict__ bias,  // 192 floats
    float* __restrict__ out)
{
    const int c4 = threadIdx.x;                            // 0..23
    const int w0 = (blockIdx.x * 4 + threadIdx.y) * WPT;   // 0..220 step 4
    const int h  = blockIdx.y;
    const int b  = blockIdx.z;

    // Kernel weights: uniform broadcast loads once, held in registers.
    float kw[3][3][2];
#pragma unroll
    for (int i = 0; i < 3; i++)
#pragma unroll
        for (int j = 0; j < 3; j++)
#pragma unroll
            for (int m = 0; m < 2; m++)
                kw[i][j][m] = __ldg(&ker[(i * 3 + j) * 2 + m]);

    // acc[j][c][m]: 4 outputs x 4 channels x 2 mult = 32 floats
    float acc[WPT][4][2];
#pragma unroll
    for (int j = 0; j < WPT; j++)
#pragma unroll
        for (int c = 0; c < 4; c++) {
            acc[j][c][0] = 0.f;
            acc[j][c][1] = 0.f;
        }

    const float4 zero4 = make_float4(0.f, 0.f, 0.f, 0.f);

#pragma unroll
    for (int dh = 0; dh < 3; dh++) {
        const int hh = h + dh - 1;
        if ((unsigned)hh < (unsigned)HH) {
            const float* rp =
                x + (((size_t)b * HH + hh) * WW + w0) * CIN + 4 * c4;

            // Load 6 consecutive w positions: w0-1 .. w0+4 (batched -> MLP=6)
            float4 v[WPT + 2];
            v[0] = (w0 >= 1) ? *reinterpret_cast<const float4*>(rp - CIN) : zero4;
#pragma unroll
            for (int t = 1; t <= WPT; t++)
                v[t] = *reinterpret_cast<const float4*>(rp + (t - 1) * CIN);
            v[WPT + 1] = (w0 + WPT < WW)
                             ? *reinterpret_cast<const float4*>(rp + WPT * CIN)
                             : zero4;

#pragma unroll
            for (int j = 0; j < WPT; j++) {
#pragma unroll
                for (int dw = 0; dw < 3; dw++) {
                    const float4 xv = v[j + dw];
#pragma unroll
                    for (int m = 0; m < 2; m++) {
                        const float k = kw[dh][dw][m];
                        acc[j][0][m] = fmaf(xv.x, k, acc[j][0][m]);
                        acc[j][1][m] = fmaf(xv.y, k, acc[j][1][m]);
                        acc[j][2][m] = fmaf(xv.z, k, acc[j][2][m]);
                        acc[j][3][m] = fmaf(xv.w, k, acc[j][3][m]);
                    }
                }
            }
        }
    }

    // bias: thread c4 covers output channels [8*c4, 8*c4+8)
    const float4 b0 = *reinterpret_cast<const float4*>(&bias[8 * c4]);
    const float4 b1 = *reinterpret_cast<const float4*>(&bias[8 * c4 + 4]);

    const size_t obase0 = (((size_t)b * HH + h) * WW + w0) * COUT + 8 * c4;
#pragma unroll
    for (int j = 0; j < WPT; j++) {
        // interleaved output ordering: oc = c*2 + m
        const float4 s0 = make_float4(acc[j][0][0] + b0.x, acc[j][0][1] + b0.y,
                                      acc[j][1][0] + b0.z, acc[j][1][1] + b0.w);
        const float4 s1 = make_float4(acc[j][2][0] + b1.x, acc[j][2][1] + b1.y,
                                      acc[j][3][0] + b1.z, acc[j][3][1] + b1.w);
        const size_t obase = obase0 + (size_t)j * COUT;
        *reinterpret_cast<float4*>(&out[obase])     = s0;
        *reinterpret_cast<float4*>(&out[obase + 4]) = s1;
    }
}

extern "C" void kernel_launch(void* const* d_in, const int* in_sizes, int n_in,
                              void* d_out, int out_size) {
    const float* x    = (const float*)d_in[0];
    const float* ker  = (const float*)d_in[1];
    const float* bias = (const float*)d_in[2];
    float* out        = (float*)d_out;

    dim3 block(24, 4, 1);
    dim3 grid(WW / (4 * WPT), HH, BATCH);
    dwconv_kernel<<<grid, block>>>(x, ker, bias, out);
}